// round 1
// baseline (speedup 1.0000x reference)
#include <cuda_runtime.h>
#include <math.h>

#define HH 256
#define WW 704
#define HWP (HH*WW)          // 180224
#define CIMG 256
#define COUT 131

// ---------------- scratch (static device globals; no allocation) ----------------
__device__ __align__(16) float g_gated[HWP];
__device__ __align__(16) float g_L[HWP];
__device__ __align__(16) float g_att[HWP];
__device__ float g_t[9*131];      // tap x 131  (also M2)
__device__ float g_M0[9*35];
__device__ float g_M1[9*67];
__device__ float g_swsum[9];
__device__ float g_gconst[9];
__device__ float g_const2[131];

// ---------------- tiny precompute: fold all 1x1 convs into per-tap matrices ------
__global__ void precompute_kernel(const float* __restrict__ W0, const float* __restrict__ b0,
                                  const float* __restrict__ W1, const float* __restrict__ b1,
                                  const float* __restrict__ W2, const float* __restrict__ b2,
                                  const float* __restrict__ spw)
{
    int tid = threadIdx.x;
    // stage 1: const2[c] = W2·(b0+b1) + b2 ; swsum[d] = sum_c spw[c,d]
    for (int c = tid; c < 131; c += blockDim.x) {
        float acc = b2[c];
        const float* w2r = W2 + c*131;
        for (int k = 0; k < 131; k++) acc += w2r[k]*(b0[k]+b1[k]);
        g_const2[c] = acc;
    }
    if (tid < 9) {
        float s = 0.f;
        for (int c = 0; c < 131; c++) s += spw[c*9+tid];
        g_swsum[tid] = s;
    }
    __syncthreads();
    // stage 2: t[d,k] = sum_c spw[c,d]*W2[c,k] ; gconst[d] = sum_c spw[c,d]*const2[c]
    for (int idx = tid; idx < 9*131; idx += blockDim.x) {
        int d = idx / 131, k = idx % 131;
        float acc = 0.f;
        for (int c = 0; c < 131; c++) acc += spw[c*9+d]*W2[c*131+k];
        g_t[idx] = acc;
    }
    if (tid < 9) {
        float s = 0.f;
        for (int c = 0; c < 131; c++) s += spw[c*9+tid]*g_const2[c];
        g_gconst[tid] = s;
    }
    __syncthreads();
    // stage 3: M0 = t·W0 (9x35), M1 = t·W1 (9x67)
    for (int idx = tid; idx < 9*35; idx += blockDim.x) {
        int d = idx/35, j = idx%35;
        float acc = 0.f;
        for (int k = 0; k < 131; k++) acc += g_t[d*131+k]*W0[k*35+j];
        g_M0[idx] = acc;
    }
    for (int idx = tid; idx < 9*67; idx += blockDim.x) {
        int d = idx/67, j = idx%67;
        float acc = 0.f;
        for (int k = 0; k < 131; k++) acc += g_t[d*131+k]*W1[k*67+j];
        g_M1[idx] = acc;
    }
}

__global__ void zeroL_kernel()
{
    int p = blockIdx.x*blockDim.x + threadIdx.x;
    if (p < HWP) g_L[p] = 0.f;
}

// ---------------- per-point scatter: 9 scalar taps -> atomicAdd into L ----------
template<int FC>   // feature channels; total dims F = FC + 3
__global__ void scatter_kernel(const float* __restrict__ feat,
                               const float* __restrict__ coord,
                               const int*   __restrict__ grid,
                               int N)
{
    constexpr int F = FC + 3;
    constexpr int R = (F + 31) / 32;
    __shared__ float sM[9*F];
    const float* M;
    if      (FC == 32)  M = g_M0;
    else if (FC == 64)  M = g_M1;
    else                M = g_t;
    for (int i = threadIdx.x; i < 9*F; i += blockDim.x) sM[i] = M[i];
    __syncthreads();

    int warp = (int)((blockIdx.x*(unsigned)blockDim.x + threadIdx.x) >> 5);
    int lane = threadIdx.x & 31;
    if (warp >= N) return;

    float x[R];
#pragma unroll
    for (int r = 0; r < R; r++) {
        int j = lane + 32*r;
        float v = 0.f;
        if (j < FC)      v = feat[(size_t)warp*FC + j];
        else if (j < F)  v = coord[(size_t)warp*3 + (j - FC)];
        x[r] = v;
    }
    int gx = grid[warp*2+0];   // col
    int gy = grid[warp*2+1];   // row

#pragma unroll
    for (int d = 0; d < 9; d++) {
        float acc = 0.f;
#pragma unroll
        for (int r = 0; r < R; r++) {
            int j = lane + 32*r;
            if (j < F) acc += sM[d*F + j]*x[r];
        }
#pragma unroll
        for (int o = 16; o > 0; o >>= 1) acc += __shfl_xor_sync(0xffffffffu, acc, o);
        if (lane == 0) {
            int dy = d/3, dx = d%3;
            int pr = gy + 1 - dy, pc = gx + 1 - dx;
            if (pr >= 0 && pr < HH && pc >= 0 && pc < WW)
                atomicAdd(&g_L[pr*WW + pc], acc);
        }
    }
}

// ---------------- gated = w3·img + b3 (256-ch reduction, float4 over pixels) ----
__global__ void gated_kernel(const float* __restrict__ img,
                             const float* __restrict__ w3,
                             const float* __restrict__ b3)
{
    __shared__ float sw[CIMG];
    for (int i = threadIdx.x; i < CIMG; i += blockDim.x) sw[i] = w3[i];
    __syncthreads();
    int p4 = blockIdx.x*blockDim.x + threadIdx.x;
    if (p4 >= HWP/4) return;
    const float4* img4 = reinterpret_cast<const float4*>(img);
    float b = b3[0];
    float4 acc = make_float4(b, b, b, b);
#pragma unroll 4
    for (int c = 0; c < CIMG; c++) {
        float4 v = img4[(size_t)c*(HWP/4) + p4];
        float wv = sw[c];
        acc.x += wv*v.x; acc.y += wv*v.y; acc.z += wv*v.z; acc.w += wv*v.w;
    }
    reinterpret_cast<float4*>(g_gated)[p4] = acc;
}

// ---------------- attention = sigmoid(spb + L + taps(gated) + border consts) ----
__global__ void attention_kernel(const float* __restrict__ spb)
{
    int p = blockIdx.x*blockDim.x + threadIdx.x;
    if (p >= HWP) return;
    int r = p / WW, c = p - r*WW;
    float acc = spb[0] + g_L[p];
#pragma unroll
    for (int d = 0; d < 9; d++) {
        int dy = d/3, dx = d%3;
        int qr = r + dy - 1, qc = c + dx - 1;
        if (qr >= 0 && qr < HH && qc >= 0 && qc < WW)
            acc += g_swsum[d]*g_gated[qr*WW + qc] + g_gconst[d];
    }
    g_att[p] = 1.f/(1.f + expf(-acc));
}

// ---------------- out = img * attention (broadcast over channels) ---------------
__global__ void mul_kernel(const float* __restrict__ img, float* __restrict__ out)
{
    int i = blockIdx.x*blockDim.x + threadIdx.x;    // float4 index, < 11534336
    const int TOT4 = CIMG*HWP/4;
    if (i >= TOT4) return;
    int c  = i / (HWP/4);
    int p4 = i - c*(HWP/4);
    float4 a = reinterpret_cast<const float4*>(g_att)[p4];
    float4 v = reinterpret_cast<const float4*>(img)[i];
    v.x *= a.x; v.y *= a.y; v.z *= a.z; v.w *= a.w;
    reinterpret_cast<float4*>(out)[i] = v;
}

extern "C" void kernel_launch(void* const* d_in, const int* in_sizes, int n_in,
                              void* d_out, int out_size)
{
    const float* img      = (const float*)d_in[0];
    const float* feat0    = (const float*)d_in[1];
    const float* coord0   = (const float*)d_in[2];
    const int*   grid0    = (const int*)  d_in[3];
    const float* feat1    = (const float*)d_in[4];
    const float* coord1   = (const float*)d_in[5];
    const int*   grid1    = (const int*)  d_in[6];
    const float* feat2    = (const float*)d_in[7];
    const float* coord2   = (const float*)d_in[8];
    const int*   grid2    = (const int*)  d_in[9];
    const float* rd0_w    = (const float*)d_in[10];
    const float* rd0_b    = (const float*)d_in[11];
    const float* rd1_w    = (const float*)d_in[12];
    const float* rd1_b    = (const float*)d_in[13];
    const float* rd2_w    = (const float*)d_in[14];
    const float* rd2_b    = (const float*)d_in[15];
    const float* rd3_w    = (const float*)d_in[16];
    const float* rd3_b    = (const float*)d_in[17];
    const float* sp_w     = (const float*)d_in[18];
    const float* sp_b     = (const float*)d_in[19];
    float* out = (float*)d_out;

    const int N0 = in_sizes[3] / 2;
    const int N1 = in_sizes[6] / 2;
    const int N2 = in_sizes[9] / 2;

    zeroL_kernel<<<HWP/256, 256>>>();
    precompute_kernel<<<1, 256>>>(rd0_w, rd0_b, rd1_w, rd1_b, rd2_w, rd2_b, sp_w);

    // 8 warps per block, one point per warp
    scatter_kernel<32 ><<<(N0 + 7)/8, 256>>>(feat0, coord0, grid0, N0);
    scatter_kernel<64 ><<<(N1 + 7)/8, 256>>>(feat1, coord1, grid1, N1);
    scatter_kernel<128><<<(N2 + 7)/8, 256>>>(feat2, coord2, grid2, N2);

    gated_kernel<<<(HWP/4 + 255)/256, 256>>>(img, rd3_w, rd3_b);
    attention_kernel<<<HWP/256, 256>>>(sp_b);
    mul_kernel<<<(CIMG*HWP/4 + 255)/256, 256>>>(img, out);
}

// round 2
// speedup vs baseline: 1.0952x; 1.0952x over previous
#include <cuda_runtime.h>
#include <math.h>

#define HH 256
#define WW 704
#define HWP (HH*WW)          // 180224
#define CIMG 256

// ---------------- scratch (static device globals; no allocation) ----------------
__device__ __align__(16) float g_gated[HWP];
__device__ __align__(16) float g_L[HWP];
__device__ __align__(16) float g_att[HWP];
__device__ float g_t[9*131];      // tap x 131  (also M2)
__device__ float g_M0[9*35];
__device__ float g_M1[9*67];
__device__ float g_swsum[9];
__device__ float g_gconst[9];
__device__ float g_const2[131];

// ------------- zero L (all blocks) + fold 1x1 convs (block 0 only) --------------
__global__ void init_kernel(const float* __restrict__ W0, const float* __restrict__ b0,
                            const float* __restrict__ W1, const float* __restrict__ b1,
                            const float* __restrict__ W2, const float* __restrict__ b2,
                            const float* __restrict__ spw)
{
    if (blockIdx.x > 0) {
        int p = (blockIdx.x - 1)*blockDim.x + threadIdx.x;
        if (p < HWP) g_L[p] = 0.f;
        return;
    }
    int tid = threadIdx.x;
    // stage 1: const2[c] = W2·(b0+b1) + b2 ; swsum[d] = sum_c spw[c,d]
    for (int c = tid; c < 131; c += blockDim.x) {
        float acc = b2[c];
        const float* w2r = W2 + c*131;
        for (int k = 0; k < 131; k++) acc += w2r[k]*(b0[k]+b1[k]);
        g_const2[c] = acc;
    }
    if (tid < 9) {
        float s = 0.f;
        for (int c = 0; c < 131; c++) s += spw[c*9+tid];
        g_swsum[tid] = s;
    }
    __syncthreads();
    // stage 2: t[d,k] = sum_c spw[c,d]*W2[c,k] ; gconst[d] = sum_c spw[c,d]*const2[c]
    for (int idx = tid; idx < 9*131; idx += blockDim.x) {
        int d = idx / 131, k = idx % 131;
        float acc = 0.f;
        for (int c = 0; c < 131; c++) acc += spw[c*9+d]*W2[c*131+k];
        g_t[idx] = acc;
    }
    if (tid < 9) {
        float s = 0.f;
        for (int c = 0; c < 131; c++) s += spw[c*9+tid]*g_const2[c];
        g_gconst[tid] = s;
    }
    __syncthreads();
    // stage 3: M0 = t·W0 (9x35), M1 = t·W1 (9x67)
    for (int idx = tid; idx < 9*35; idx += blockDim.x) {
        int d = idx/35, j = idx%35;
        float acc = 0.f;
        for (int k = 0; k < 131; k++) acc += g_t[d*131+k]*W0[k*35+j];
        g_M0[idx] = acc;
    }
    for (int idx = tid; idx < 9*67; idx += blockDim.x) {
        int d = idx/67, j = idx%67;
        float acc = 0.f;
        for (int k = 0; k < 131; k++) acc += g_t[d*131+k]*W1[k*67+j];
        g_M1[idx] = acc;
    }
}

// ---------------- per-point scatter: tile in shared, thread = (point, tap) ------
// block = 288 threads, 32 points per block. Each thread computes one length-F dot
// from shared memory and issues one atomicAdd. All loads coalesced, no shuffles.
template<int FC>   // feature channels; total dims F = FC + 3
__global__ __launch_bounds__(288) void scatter_kernel(const float* __restrict__ feat,
                                                      const float* __restrict__ coord,
                                                      const int*   __restrict__ grid,
                                                      int N)
{
    constexpr int F = FC + 3;
    __shared__ float sX[32*F];
    __shared__ float sM[9*F];
    __shared__ int   sG[64];

    const float* M;
    if      (FC == 32)  M = g_M0;
    else if (FC == 64)  M = g_M1;
    else                M = g_t;

    const int tid = threadIdx.x;
    const int p0  = blockIdx.x * 32;
    const int npts = min(32, N - p0);

    // coalesced loads into shared
    for (int i = tid; i < 9*F; i += 288) sM[i] = M[i];
    for (int i = tid; i < npts*FC; i += 288) {
        int pt = i / FC, j = i - pt*FC;
        sX[pt*F + j] = feat[(size_t)(p0 + pt)*FC + j];
    }
    for (int i = tid; i < npts*3; i += 288) {
        int pt = i / 3, j = i - pt*3;
        sX[pt*F + FC + j] = coord[(size_t)(p0 + pt)*3 + j];
    }
    for (int i = tid; i < npts*2; i += 288) sG[i] = grid[p0*2 + i];
    __syncthreads();

    const int pt = tid / 9;      // 0..31
    const int d  = tid - pt*9;   // 0..8
    if (pt >= npts) return;

    const float* xr = &sX[pt*F];
    const float* mr = &sM[d*F];
    float a0 = 0.f, a1 = 0.f, a2 = 0.f, a3 = 0.f;
    int k = 0;
#pragma unroll
    for (; k + 4 <= F; k += 4) {
        a0 += mr[k+0]*xr[k+0];
        a1 += mr[k+1]*xr[k+1];
        a2 += mr[k+2]*xr[k+2];
        a3 += mr[k+3]*xr[k+3];
    }
#pragma unroll
    for (; k < F; k++) a0 += mr[k]*xr[k];
    float acc = (a0 + a1) + (a2 + a3);

    const int gx = sG[pt*2+0];   // col
    const int gy = sG[pt*2+1];   // row
    const int dy = d/3, dx = d - 3*(d/3);
    const int pr = gy + 1 - dy, pc = gx + 1 - dx;
    if (pr >= 0 && pr < HH && pc >= 0 && pc < WW)
        atomicAdd(&g_L[pr*WW + pc], acc);
}

// ---------------- gated = w3·img + b3 (256-ch reduction, float4 over pixels) ----
__global__ void gated_kernel(const float* __restrict__ img,
                             const float* __restrict__ w3,
                             const float* __restrict__ b3)
{
    __shared__ float sw[CIMG];
    for (int i = threadIdx.x; i < CIMG; i += blockDim.x) sw[i] = w3[i];
    __syncthreads();
    int p4 = blockIdx.x*blockDim.x + threadIdx.x;
    if (p4 >= HWP/4) return;
    const float4* img4 = reinterpret_cast<const float4*>(img);
    float4 acc0 = make_float4(0.f, 0.f, 0.f, 0.f);
    float4 acc1 = make_float4(0.f, 0.f, 0.f, 0.f);
#pragma unroll 8
    for (int c = 0; c < CIMG; c += 2) {
        float4 v0 = img4[(size_t)c*(HWP/4) + p4];
        float4 v1 = img4[(size_t)(c+1)*(HWP/4) + p4];
        float w0 = sw[c], w1 = sw[c+1];
        acc0.x += w0*v0.x; acc0.y += w0*v0.y; acc0.z += w0*v0.z; acc0.w += w0*v0.w;
        acc1.x += w1*v1.x; acc1.y += w1*v1.y; acc1.z += w1*v1.z; acc1.w += w1*v1.w;
    }
    float b = b3[0];
    float4 r = make_float4(b + acc0.x + acc1.x, b + acc0.y + acc1.y,
                           b + acc0.z + acc1.z, b + acc0.w + acc1.w);
    reinterpret_cast<float4*>(g_gated)[p4] = r;
}

// ---------------- attention = sigmoid(spb + L + taps(gated) + border consts) ----
__global__ void attention_kernel(const float* __restrict__ spb)
{
    int p = blockIdx.x*blockDim.x + threadIdx.x;
    if (p >= HWP) return;
    int r = p / WW, c = p - r*WW;
    float acc = spb[0] + g_L[p];
#pragma unroll
    for (int d = 0; d < 9; d++) {
        int dy = d/3, dx = d%3;
        int qr = r + dy - 1, qc = c + dx - 1;
        if (qr >= 0 && qr < HH && qc >= 0 && qc < WW)
            acc += g_swsum[d]*g_gated[qr*WW + qc] + g_gconst[d];
    }
    g_att[p] = 1.f/(1.f + expf(-acc));
}

// ---------------- out = img * attention (broadcast over channels) ---------------
__global__ void mul_kernel(const float* __restrict__ img, float* __restrict__ out)
{
    int i = blockIdx.x*blockDim.x + threadIdx.x;    // float4 index
    const int TOT4 = CIMG*HWP/4;
    if (i >= TOT4) return;
    int c  = i / (HWP/4);
    int p4 = i - c*(HWP/4);
    float4 a = reinterpret_cast<const float4*>(g_att)[p4];
    float4 v = reinterpret_cast<const float4*>(img)[i];
    v.x *= a.x; v.y *= a.y; v.z *= a.z; v.w *= a.w;
    reinterpret_cast<float4*>(out)[i] = v;
}

extern "C" void kernel_launch(void* const* d_in, const int* in_sizes, int n_in,
                              void* d_out, int out_size)
{
    const float* img      = (const float*)d_in[0];
    const float* feat0    = (const float*)d_in[1];
    const float* coord0   = (const float*)d_in[2];
    const int*   grid0    = (const int*)  d_in[3];
    const float* feat1    = (const float*)d_in[4];
    const float* coord1   = (const float*)d_in[5];
    const int*   grid1    = (const int*)  d_in[6];
    const float* feat2    = (const float*)d_in[7];
    const float* coord2   = (const float*)d_in[8];
    const int*   grid2    = (const int*)  d_in[9];
    const float* rd0_w    = (const float*)d_in[10];
    const float* rd0_b    = (const float*)d_in[11];
    const float* rd1_w    = (const float*)d_in[12];
    const float* rd1_b    = (const float*)d_in[13];
    const float* rd2_w    = (const float*)d_in[14];
    const float* rd2_b    = (const float*)d_in[15];
    const float* rd3_w    = (const float*)d_in[16];
    const float* rd3_b    = (const float*)d_in[17];
    const float* sp_w     = (const float*)d_in[18];
    const float* sp_b     = (const float*)d_in[19];
    float* out = (float*)d_out;

    const int N0 = in_sizes[3] / 2;
    const int N1 = in_sizes[6] / 2;
    const int N2 = in_sizes[9] / 2;

    // zero L + fold weights in one launch (block 0 = precompute)
    init_kernel<<<1 + HWP/256, 256>>>(rd0_w, rd0_b, rd1_w, rd1_b, rd2_w, rd2_b, sp_w);

    // 32 points per block, thread = (point, tap)
    scatter_kernel<32 ><<<(N0 + 31)/32, 288>>>(feat0, coord0, grid0, N0);
    scatter_kernel<64 ><<<(N1 + 31)/32, 288>>>(feat1, coord1, grid1, N1);
    scatter_kernel<128><<<(N2 + 31)/32, 288>>>(feat2, coord2, grid2, N2);

    gated_kernel<<<(HWP/4 + 255)/256, 256>>>(img, rd3_w, rd3_b);
    attention_kernel<<<HWP/256, 256>>>(sp_b);
    mul_kernel<<<(CIMG*HWP/4 + 255)/256, 256>>>(img, out);
}

// round 3
// speedup vs baseline: 1.3005x; 1.1874x over previous
#include <cuda_runtime.h>
#include <math.h>

#define HH 256
#define WW 704
#define HWP (HH*WW)          // 180224
#define CIMG 256

// ---------------- scratch (static device globals; no allocation) ----------------
__device__ __align__(16) float g_gated[HWP];
__device__ __align__(16) float g_L[HWP];
__device__ float g_t[9*131];
__device__ float g_M0[9*35];
__device__ float g_M1[9*67];
__device__ float g_swsum[9];
__device__ float g_gconst[9];
__device__ float g_const2[131];
// padded float4 matrices (feature part) + coord parts
__device__ __align__(16) float4 g_M4_0[9*8];    // FC=32
__device__ __align__(16) float4 g_M4_1[9*16];   // FC=64
__device__ __align__(16) float4 g_M4_2[9*32];   // FC=128
__device__ float g_C0[27], g_C1[27], g_C2[27];  // [d][3] coord weights

// ------------- zero L (blocks >0) + fold 1x1 convs (block 0 only) --------------
__global__ void init_kernel(const float* __restrict__ W0, const float* __restrict__ b0,
                            const float* __restrict__ W1, const float* __restrict__ b1,
                            const float* __restrict__ W2, const float* __restrict__ b2,
                            const float* __restrict__ spw)
{
    if (blockIdx.x > 0) {
        int p = (blockIdx.x - 1)*blockDim.x + threadIdx.x;
        if (p < HWP) g_L[p] = 0.f;
        return;
    }
    int tid = threadIdx.x;
    // stage 1: const2[c] = W2·(b0+b1) + b2 ; swsum[d] = sum_c spw[c,d]
    for (int c = tid; c < 131; c += blockDim.x) {
        float acc = b2[c];
        const float* w2r = W2 + c*131;
        for (int k = 0; k < 131; k++) acc += w2r[k]*(b0[k]+b1[k]);
        g_const2[c] = acc;
    }
    if (tid < 9) {
        float s = 0.f;
        for (int c = 0; c < 131; c++) s += spw[c*9+tid];
        g_swsum[tid] = s;
    }
    __syncthreads();
    // stage 2: t[d,k] = sum_c spw[c,d]*W2[c,k] ; gconst[d] = spw[:,d]·const2
    for (int idx = tid; idx < 9*131; idx += blockDim.x) {
        int d = idx / 131, k = idx % 131;
        float acc = 0.f;
        for (int c = 0; c < 131; c++) acc += spw[c*9+d]*W2[c*131+k];
        g_t[idx] = acc;
    }
    if (tid < 9) {
        float s = 0.f;
        for (int c = 0; c < 131; c++) s += spw[c*9+tid]*g_const2[c];
        g_gconst[tid] = s;
    }
    __syncthreads();
    // stage 3: M0 = t·W0 (9x35), M1 = t·W1 (9x67)
    for (int idx = tid; idx < 9*35; idx += blockDim.x) {
        int d = idx/35, j = idx%35;
        float acc = 0.f;
        for (int k = 0; k < 131; k++) acc += g_t[d*131+k]*W0[k*35+j];
        g_M0[idx] = acc;
    }
    for (int idx = tid; idx < 9*67; idx += blockDim.x) {
        int d = idx/67, j = idx%67;
        float acc = 0.f;
        for (int k = 0; k < 131; k++) acc += g_t[d*131+k]*W1[k*67+j];
        g_M1[idx] = acc;
    }
    __syncthreads();
    // stage 4: repack into padded float4 layout + coord tails
    for (int i = tid; i < 9*8*4; i += blockDim.x) {
        int d = i/32, j = i%32;
        reinterpret_cast<float*>(g_M4_0)[i] = g_M0[d*35 + j];
    }
    for (int i = tid; i < 9*16*4; i += blockDim.x) {
        int d = i/64, j = i%64;
        reinterpret_cast<float*>(g_M4_1)[i] = g_M1[d*67 + j];
    }
    for (int i = tid; i < 9*32*4; i += blockDim.x) {
        int d = i/128, j = i%128;
        reinterpret_cast<float*>(g_M4_2)[i] = g_t[d*131 + j];
    }
    if (tid < 27) {
        int d = tid/3, j = tid%3;
        g_C0[tid] = g_M0[d*35 + 32 + j];
        g_C1[tid] = g_M1[d*67 + 64 + j];
        g_C2[tid] = g_t [d*131 + 128 + j];
    }
}

// ---------------- scatter body: thread = point, 9 accumulators ------------------
template<int FC>
__device__ __forceinline__ void scatter_body(const float* __restrict__ feat,
                                             const float* __restrict__ coord,
                                             const int*   __restrict__ grid,
                                             int N, const float4* __restrict__ M4g,
                                             const float* __restrict__ Cg, int blk)
{
    constexpr int K4 = FC/4;
    __shared__ float4 sM4[9*32];
    __shared__ float  sC[27];
    const int tid = threadIdx.x;
    for (int i = tid; i < 9*K4; i += 256) sM4[i] = M4g[i];
    if (tid < 27) sC[tid] = Cg[tid];
    __syncthreads();

    const int pt = blk*256 + tid;
    if (pt >= N) return;

    float acc[9];
#pragma unroll
    for (int d = 0; d < 9; d++) acc[d] = 0.f;

    const float4* xf = reinterpret_cast<const float4*>(feat) + (size_t)pt*K4;
#pragma unroll 4
    for (int k4 = 0; k4 < K4; k4++) {
        float4 x = xf[k4];
#pragma unroll
        for (int d = 0; d < 9; d++) {
            float4 m = sM4[d*K4 + k4];
            acc[d] += m.x*x.x + m.y*x.y + m.z*x.z + m.w*x.w;
        }
    }
    float c0 = coord[3*(size_t)pt+0], c1 = coord[3*(size_t)pt+1], c2 = coord[3*(size_t)pt+2];
#pragma unroll
    for (int d = 0; d < 9; d++)
        acc[d] += sC[d*3+0]*c0 + sC[d*3+1]*c1 + sC[d*3+2]*c2;

    const int gx = grid[2*pt+0];   // col
    const int gy = grid[2*pt+1];   // row
#pragma unroll
    for (int d = 0; d < 9; d++) {
        int dy = d/3, dx = d - 3*dy;
        int pr = gy + 1 - dy, pc = gx + 1 - dx;
        if (pr >= 0 && pr < HH && pc >= 0 && pc < WW)
            atomicAdd(&g_L[pr*WW + pc], acc[d]);
    }
}

// ---------------- gated body: g_gated = w3·img + b3 ----------------------------
__device__ __forceinline__ void gated_body(const float* __restrict__ img,
                                           const float* __restrict__ w3,
                                           const float* __restrict__ b3, int blk)
{
    __shared__ float sw[CIMG];
    for (int i = threadIdx.x; i < CIMG; i += 256) sw[i] = w3[i];
    __syncthreads();
    int p4 = blk*256 + threadIdx.x;          // < HWP/4 = 45056 exactly
    const float4* img4 = reinterpret_cast<const float4*>(img);
    float4 acc0 = make_float4(0.f,0.f,0.f,0.f);
    float4 acc1 = make_float4(0.f,0.f,0.f,0.f);
#pragma unroll 8
    for (int c = 0; c < CIMG; c += 2) {
        float4 v0 = img4[(size_t)c*(HWP/4) + p4];
        float4 v1 = img4[(size_t)(c+1)*(HWP/4) + p4];
        float w0 = sw[c], w1 = sw[c+1];
        acc0.x += w0*v0.x; acc0.y += w0*v0.y; acc0.z += w0*v0.z; acc0.w += w0*v0.w;
        acc1.x += w1*v1.x; acc1.y += w1*v1.y; acc1.z += w1*v1.z; acc1.w += w1*v1.w;
    }
    float b = b3[0];
    float4 r = make_float4(b + acc0.x + acc1.x, b + acc0.y + acc1.y,
                           b + acc0.z + acc1.z, b + acc0.w + acc1.w);
    reinterpret_cast<float4*>(g_gated)[p4] = r;
}

// ---------------- fused kernel: gated blocks || scatter blocks ------------------
#define GB (HWP/4/256)   // 176
__global__ __launch_bounds__(256) void fused_kernel(
    const float* __restrict__ img, const float* __restrict__ w3, const float* __restrict__ b3,
    const float* __restrict__ f0, const float* __restrict__ c0, const int* __restrict__ gr0, int N0, int NB0,
    const float* __restrict__ f1, const float* __restrict__ c1, const int* __restrict__ gr1, int N1, int NB1,
    const float* __restrict__ f2, const float* __restrict__ c2, const int* __restrict__ gr2, int N2)
{
    int b = blockIdx.x;
    if (b < GB) { gated_body(img, w3, b3, b); return; }
    b -= GB;
    if (b < NB0) { scatter_body<32>(f0, c0, gr0, N0, g_M4_0, g_C0, b); return; }
    b -= NB0;
    if (b < NB1) { scatter_body<64>(f1, c1, gr1, N1, g_M4_1, g_C1, b); return; }
    b -= NB1;
    scatter_body<128>(f2, c2, gr2, N2, g_M4_2, g_C2, b);
}

// ---------------- attention (256-px tile in shared) + multiply ------------------
__global__ __launch_bounds__(256) void attmul_kernel(const float* __restrict__ img,
                                                     float* __restrict__ out,
                                                     const float* __restrict__ spb)
{
    __shared__ float sAtt[256];
    const int tid = threadIdx.x;
    const int p0  = blockIdx.x * 256;
    const int p   = p0 + tid;
    {
        int r = p / WW, c = p - r*WW;
        float acc = spb[0] + g_L[p];
#pragma unroll
        for (int d = 0; d < 9; d++) {
            int dy = d/3, dx = d%3;
            int qr = r + dy - 1, qc = c + dx - 1;
            if (qr >= 0 && qr < HH && qc >= 0 && qc < WW)
                acc += g_swsum[d]*g_gated[qr*WW + qc] + g_gconst[d];
        }
        sAtt[tid] = 1.f/(1.f + expf(-acc));
    }
    __syncthreads();

    const float4* img4 = reinterpret_cast<const float4*>(img);
    float4*       out4 = reinterpret_cast<float4*>(out);
    const float4* sA4  = reinterpret_cast<const float4*>(sAtt);
    const int base4 = p0 >> 2;                // 64 float4 per tile
    const int f  = tid & 63;
    const int cb = tid >> 6;                  // 0..3
    const float4 a = sA4[f];
#pragma unroll 4
    for (int it = 0; it < 64; it++) {
        int c = it*4 + cb;
        size_t i = (size_t)c*(HWP/4) + base4 + f;
        float4 v = img4[i];
        v.x *= a.x; v.y *= a.y; v.z *= a.z; v.w *= a.w;
        out4[i] = v;
    }
}

extern "C" void kernel_launch(void* const* d_in, const int* in_sizes, int n_in,
                              void* d_out, int out_size)
{
    const float* img      = (const float*)d_in[0];
    const float* feat0    = (const float*)d_in[1];
    const float* coord0   = (const float*)d_in[2];
    const int*   grid0    = (const int*)  d_in[3];
    const float* feat1    = (const float*)d_in[4];
    const float* coord1   = (const float*)d_in[5];
    const int*   grid1    = (const int*)  d_in[6];
    const float* feat2    = (const float*)d_in[7];
    const float* coord2   = (const float*)d_in[8];
    const int*   grid2    = (const int*)  d_in[9];
    const float* rd0_w    = (const float*)d_in[10];
    const float* rd0_b    = (const float*)d_in[11];
    const float* rd1_w    = (const float*)d_in[12];
    const float* rd1_b    = (const float*)d_in[13];
    const float* rd2_w    = (const float*)d_in[14];
    const float* rd2_b    = (const float*)d_in[15];
    const float* rd3_w    = (const float*)d_in[16];
    const float* rd3_b    = (const float*)d_in[17];
    const float* sp_w     = (const float*)d_in[18];
    const float* sp_b     = (const float*)d_in[19];
    float* out = (float*)d_out;

    const int N0 = in_sizes[3] / 2;
    const int N1 = in_sizes[6] / 2;
    const int N2 = in_sizes[9] / 2;
    const int NB0 = (N0 + 255)/256;
    const int NB1 = (N1 + 255)/256;
    const int NB2 = (N2 + 255)/256;

    init_kernel<<<1 + HWP/256, 256>>>(rd0_w, rd0_b, rd1_w, rd1_b, rd2_w, rd2_b, sp_w);

    fused_kernel<<<GB + NB0 + NB1 + NB2, 256>>>(
        img, rd3_w, rd3_b,
        feat0, coord0, grid0, N0, NB0,
        feat1, coord1, grid1, N1, NB1,
        feat2, coord2, grid2, N2);

    attmul_kernel<<<HWP/256, 256>>>(img, out, sp_b);
}

// round 4
// speedup vs baseline: 1.7379x; 1.3363x over previous
#include <cuda_runtime.h>
#include <math.h>

#define HH 256
#define WW 704
#define HWP (HH*WW)          // 180224
#define CIMG 256

// ---------------- scratch (static device globals; no allocation) ----------------
__device__ __align__(16) float g_gated[HWP];
__device__ __align__(16) float g_L[HWP];
__device__ float g_t[9*131];
__device__ float g_swsum[9];
__device__ float g_gconst[9];
__device__ float g_const2[131];
// padded float4 matrices (feature part) + coord parts
__device__ __align__(16) float4 g_M4_0[9*8];    // FC=32
__device__ __align__(16) float4 g_M4_1[9*16];   // FC=64
__device__ __align__(16) float4 g_M4_2[9*32];   // FC=128
__device__ float g_C0[27], g_C1[27], g_C2[27];  // [d][3] coord weights

__device__ __forceinline__ float warp_red(float s) {
#pragma unroll
    for (int o = 16; o > 0; o >>= 1) s += __shfl_xor_sync(0xffffffffu, s, o);
    return s;
}

// ---------------- initA: zero L (blocks < 704) + warp-dot tasks -----------------
// warp tasks: [0,131): const2[c] ; [131,140): swsum[d] ; [140,1319): t[d,k]
#define ZB (HWP/256)            // 704
#define NTA 1319
__global__ __launch_bounds__(256) void initA_kernel(
    const float* __restrict__ W2, const float* __restrict__ b2,
    const float* __restrict__ b0, const float* __restrict__ b1,
    const float* __restrict__ spw)
{
    int b = blockIdx.x;
    if (b < ZB) {
        g_L[b*256 + threadIdx.x] = 0.f;
        return;
    }
    int task = (b - ZB)*8 + (threadIdx.x >> 5);
    int lane = threadIdx.x & 31;
    if (task >= NTA) return;

    if (task < 131) {
        int c = task;
        float s = 0.f;
        for (int k = lane; k < 131; k += 32) s += W2[c*131+k]*(b0[k]+b1[k]);
        s = warp_red(s);
        if (lane == 0) g_const2[c] = s + b2[c];
    } else if (task < 140) {
        int d = task - 131;
        float s = 0.f;
        for (int c = lane; c < 131; c += 32) s += spw[c*9+d];
        s = warp_red(s);
        if (lane == 0) g_swsum[d] = s;
    } else {
        int idx = task - 140;
        int d = idx / 131, k = idx - d*131;
        float s = 0.f;
        for (int c = lane; c < 131; c += 32) s += spw[c*9+d]*W2[c*131+k];
        s = warp_red(s);
        if (lane == 0) g_t[idx] = s;
    }
}

// ---------------- initB: gconst + M0/M1 (packed) + pack t -----------------------
// warp tasks: [0,9): gconst ; [9,324): M0[d,j] ; [324,927): M1[d,j]
#define NTB 927
#define NBB ((NTB + 7)/8)       // 116
__global__ __launch_bounds__(256) void initB_kernel(
    const float* __restrict__ W0, const float* __restrict__ W1,
    const float* __restrict__ spw)
{
    int b = blockIdx.x;
    if (b == NBB) {  // pack t -> M4_2 / C2
        for (int i = threadIdx.x; i < 9*131; i += 256) {
            int d = i / 131, j = i - d*131;
            float v = g_t[i];
            if (j < 128) reinterpret_cast<float*>(g_M4_2)[d*128 + j] = v;
            else         g_C2[d*3 + (j - 128)] = v;
        }
        return;
    }
    int task = b*8 + (threadIdx.x >> 5);
    int lane = threadIdx.x & 31;
    if (task >= NTB) return;

    if (task < 9) {
        int d = task;
        float s = 0.f;
        for (int c = lane; c < 131; c += 32) s += spw[c*9+d]*g_const2[c];
        s = warp_red(s);
        if (lane == 0) g_gconst[d] = s;
    } else if (task < 324) {
        int idx = task - 9;
        int d = idx / 35, j = idx - d*35;
        float s = 0.f;
        for (int k = lane; k < 131; k += 32) s += g_t[d*131+k]*W0[k*35+j];
        s = warp_red(s);
        if (lane == 0) {
            if (j < 32) reinterpret_cast<float*>(g_M4_0)[d*32 + j] = s;
            else        g_C0[d*3 + (j - 32)] = s;
        }
    } else {
        int idx = task - 324;
        int d = idx / 67, j = idx - d*67;
        float s = 0.f;
        for (int k = lane; k < 131; k += 32) s += g_t[d*131+k]*W1[k*67+j];
        s = warp_red(s);
        if (lane == 0) {
            if (j < 64) reinterpret_cast<float*>(g_M4_1)[d*64 + j] = s;
            else        g_C1[d*3 + (j - 64)] = s;
        }
    }
}

// ---------------- scatter body: thread = point, 9 accumulators ------------------
template<int FC>
__device__ __forceinline__ void scatter_body(const float* __restrict__ feat,
                                             const float* __restrict__ coord,
                                             const int*   __restrict__ grid,
                                             int N, const float4* __restrict__ M4g,
                                             const float* __restrict__ Cg, int blk)
{
    constexpr int K4 = FC/4;
    __shared__ float4 sM4[9*32];
    __shared__ float  sC[27];
    const int tid = threadIdx.x;
    for (int i = tid; i < 9*K4; i += 256) sM4[i] = M4g[i];
    if (tid < 27) sC[tid] = Cg[tid];
    __syncthreads();

    const int pt = blk*256 + tid;
    if (pt >= N) return;

    float acc[9];
#pragma unroll
    for (int d = 0; d < 9; d++) acc[d] = 0.f;

    const float4* xf = reinterpret_cast<const float4*>(feat) + (size_t)pt*K4;
#pragma unroll 4
    for (int k4 = 0; k4 < K4; k4++) {
        float4 x = xf[k4];
#pragma unroll
        for (int d = 0; d < 9; d++) {
            float4 m = sM4[d*K4 + k4];
            acc[d] += m.x*x.x + m.y*x.y + m.z*x.z + m.w*x.w;
        }
    }
    float c0 = coord[3*(size_t)pt+0], c1 = coord[3*(size_t)pt+1], c2 = coord[3*(size_t)pt+2];
#pragma unroll
    for (int d = 0; d < 9; d++)
        acc[d] += sC[d*3+0]*c0 + sC[d*3+1]*c1 + sC[d*3+2]*c2;

    const int gx = grid[2*pt+0];   // col
    const int gy = grid[2*pt+1];   // row
#pragma unroll
    for (int d = 0; d < 9; d++) {
        int dy = d/3, dx = d - 3*dy;
        int pr = gy + 1 - dy, pc = gx + 1 - dx;
        if (pr >= 0 && pr < HH && pc >= 0 && pc < WW)
            atomicAdd(&g_L[pr*WW + pc], acc[d]);
    }
}

// ---------------- gated body: g_gated = w3·img + b3 ----------------------------
__device__ __forceinline__ void gated_body(const float* __restrict__ img,
                                           const float* __restrict__ w3,
                                           const float* __restrict__ b3, int blk)
{
    __shared__ float sw[CIMG];
    for (int i = threadIdx.x; i < CIMG; i += 256) sw[i] = w3[i];
    __syncthreads();
    int p4 = blk*256 + threadIdx.x;          // < HWP/4 = 45056 exactly
    const float4* img4 = reinterpret_cast<const float4*>(img);
    float4 acc0 = make_float4(0.f,0.f,0.f,0.f);
    float4 acc1 = make_float4(0.f,0.f,0.f,0.f);
#pragma unroll 8
    for (int c = 0; c < CIMG; c += 2) {
        float4 v0 = img4[(size_t)c*(HWP/4) + p4];
        float4 v1 = img4[(size_t)(c+1)*(HWP/4) + p4];
        float w0 = sw[c], w1 = sw[c+1];
        acc0.x += w0*v0.x; acc0.y += w0*v0.y; acc0.z += w0*v0.z; acc0.w += w0*v0.w;
        acc1.x += w1*v1.x; acc1.y += w1*v1.y; acc1.z += w1*v1.z; acc1.w += w1*v1.w;
    }
    float b = b3[0];
    float4 r = make_float4(b + acc0.x + acc1.x, b + acc0.y + acc1.y,
                           b + acc0.z + acc1.z, b + acc0.w + acc1.w);
    reinterpret_cast<float4*>(g_gated)[p4] = r;
}

// ---------------- fused kernel: gated blocks || scatter blocks ------------------
#define GB (HWP/4/256)   // 176
__global__ __launch_bounds__(256) void fused_kernel(
    const float* __restrict__ img, const float* __restrict__ w3, const float* __restrict__ b3,
    const float* __restrict__ f0, const float* __restrict__ c0, const int* __restrict__ gr0, int N0, int NB0,
    const float* __restrict__ f1, const float* __restrict__ c1, const int* __restrict__ gr1, int N1, int NB1,
    const float* __restrict__ f2, const float* __restrict__ c2, const int* __restrict__ gr2, int N2)
{
    int b = blockIdx.x;
    if (b < GB) { gated_body(img, w3, b3, b); return; }
    b -= GB;
    if (b < NB0) { scatter_body<32>(f0, c0, gr0, N0, g_M4_0, g_C0, b); return; }
    b -= NB0;
    if (b < NB1) { scatter_body<64>(f1, c1, gr1, N1, g_M4_1, g_C1, b); return; }
    b -= NB1;
    scatter_body<128>(f2, c2, gr2, N2, g_M4_2, g_C2, b);
}

// ---------------- attention (256-px tile in shared) + multiply ------------------
__global__ __launch_bounds__(256) void attmul_kernel(const float* __restrict__ img,
                                                     float* __restrict__ out,
                                                     const float* __restrict__ spb)
{
    __shared__ float sAtt[256];
    const int tid = threadIdx.x;
    const int p0  = blockIdx.x * 256;
    const int p   = p0 + tid;
    {
        int r = p / WW, c = p - r*WW;
        float acc = spb[0] + g_L[p];
#pragma unroll
        for (int d = 0; d < 9; d++) {
            int dy = d/3, dx = d%3;
            int qr = r + dy - 1, qc = c + dx - 1;
            if (qr >= 0 && qr < HH && qc >= 0 && qc < WW)
                acc += g_swsum[d]*g_gated[qr*WW + qc] + g_gconst[d];
        }
        sAtt[tid] = 1.f/(1.f + expf(-acc));
    }
    __syncthreads();

    const float4* img4 = reinterpret_cast<const float4*>(img);
    float4*       out4 = reinterpret_cast<float4*>(out);
    const float4* sA4  = reinterpret_cast<const float4*>(sAtt);
    const int base4 = p0 >> 2;                // 64 float4 per tile
    const int f  = tid & 63;
    const int cb = tid >> 6;                  // 0..3
    const float4 a = sA4[f];
#pragma unroll 4
    for (int it = 0; it < 64; it++) {
        int c = it*4 + cb;
        size_t i = (size_t)c*(HWP/4) + base4 + f;
        float4 v = img4[i];
        v.x *= a.x; v.y *= a.y; v.z *= a.z; v.w *= a.w;
        out4[i] = v;
    }
}

extern "C" void kernel_launch(void* const* d_in, const int* in_sizes, int n_in,
                              void* d_out, int out_size)
{
    const float* img      = (const float*)d_in[0];
    const float* feat0    = (const float*)d_in[1];
    const float* coord0   = (const float*)d_in[2];
    const int*   grid0    = (const int*)  d_in[3];
    const float* feat1    = (const float*)d_in[4];
    const float* coord1   = (const float*)d_in[5];
    const int*   grid1    = (const int*)  d_in[6];
    const float* feat2    = (const float*)d_in[7];
    const float* coord2   = (const float*)d_in[8];
    const int*   grid2    = (const int*)  d_in[9];
    const float* rd0_w    = (const float*)d_in[10];
    const float* rd0_b    = (const float*)d_in[11];
    const float* rd1_w    = (const float*)d_in[12];
    const float* rd1_b    = (const float*)d_in[13];
    const float* rd2_w    = (const float*)d_in[14];
    const float* rd2_b    = (const float*)d_in[15];
    const float* rd3_w    = (const float*)d_in[16];
    const float* rd3_b    = (const float*)d_in[17];
    const float* sp_w     = (const float*)d_in[18];
    const float* sp_b     = (const float*)d_in[19];
    float* out = (float*)d_out;

    const int N0 = in_sizes[3] / 2;
    const int N1 = in_sizes[6] / 2;
    const int N2 = in_sizes[9] / 2;
    const int NB0 = (N0 + 255)/256;
    const int NB1 = (N1 + 255)/256;
    const int NB2 = (N2 + 255)/256;

    initA_kernel<<<ZB + (NTA + 7)/8, 256>>>(rd2_w, rd2_b, rd0_b, rd1_b, sp_w);
    initB_kernel<<<NBB + 1, 256>>>(rd0_w, rd1_w, sp_w);

    fused_kernel<<<GB + NB0 + NB1 + NB2, 256>>>(
        img, rd3_w, rd3_b,
        feat0, coord0, grid0, N0, NB0,
        feat1, coord1, grid1, N1, NB1,
        feat2, coord2, grid2, N2);

    attmul_kernel<<<HWP/256, 256>>>(img, out, sp_b);
}